// round 16
// baseline (speedup 1.0000x reference)
#include <cuda_runtime.h>
#include <cuda_fp16.h>
#include <cstdint>

#define CIN   128
#define CHID  256
#define COUT  128
#define HW    1600
#define TP    32
#define NT    256
#define NTILE 50

#define SXW 40     // x row stride in u32 words (mod 32 == 8 -> conflict-free LDS.64)
#define SHW 40     // h row stride

// SMEM u32-word offsets
#define OXS 0                        // x [64 kpair][40] u32 (fp16x2, px pair-permuted)
#define OHB 2560                     // h: 2 bufs x [32 kpair][40]
#define HBSZ 1280
#define OGB 5120                     // gated b2 [128] (float view)
#define SMB ((5120 + 128) * 4)       // 20992 B -> 3 CTAs/SM (regs permitting)

// weights packed as fp16 MMA A-fragments (one uint4 per lane per k16-step), 512KB each
__device__ uint4 sW1h[32768];
__device__ uint4 sW2h[32768];
__device__ int   g_idx[256];

__device__ __forceinline__ uint32_t pkh(float a, float b) {
    __half2 h = __floats2half2_rn(a, b);   // low = a
    return *reinterpret_cast<uint32_t*>(&h);
}
__device__ __forceinline__ void mmah(float (&d)[4], const uint4& a, uint32_t b0, uint32_t b1) {
    asm("mma.sync.aligned.m16n8k16.row.col.f32.f16.f16.f32 "
        "{%0,%1,%2,%3}, {%4,%5,%6,%7}, {%8,%9}, {%0,%1,%2,%3};"
        : "+f"(d[0]), "+f"(d[1]), "+f"(d[2]), "+f"(d[3])
        : "r"(a.x), "r"(a.y), "r"(a.z), "r"(a.w), "r"(b0), "r"(b1));
}

__global__ void prep_idx(const int* __restrict__ raw) {
    __shared__ int odd_nz;
    if (threadIdx.x == 0) odd_nz = 0;
    __syncthreads();
    if (threadIdx.x < 128) {
        if (raw[2 * threadIdx.x + 1] != 0) atomicAdd(&odd_nz, 1);
    }
    __syncthreads();
    bool is64 = (odd_nz == 0);
    g_idx[threadIdx.x] = is64 ? raw[2 * threadIdx.x] : raw[threadIdx.x];
}

// Pack weights into fp16 A-fragment order (identical layout to R14/R15).
__global__ void prep_wh(const float* __restrict__ W1, const float* __restrict__ W2) {
    int tid = blockIdx.x * blockDim.x + threadIdx.x;    // 0..32767
    int lane = tid & 31, g = lane >> 2, t = lane & 3;
    {
        int ks = (tid >> 5) & 7, wm = (tid >> 8) & 3, j = (tid >> 10) & 3, e = (tid >> 12) & 7;
        const float* s = W1 + (size_t)e * 32768;
        int ch = j * 64 + wm * 16 + g;
        int c0 = ks * 16 + 2 * t;
        uint4 v;
        v.x = pkh(s[ch * 128 + c0],           s[ch * 128 + c0 + 1]);
        v.y = pkh(s[(ch + 8) * 128 + c0],     s[(ch + 8) * 128 + c0 + 1]);
        v.z = pkh(s[ch * 128 + c0 + 8],       s[ch * 128 + c0 + 9]);
        v.w = pkh(s[(ch + 8) * 128 + c0 + 8], s[(ch + 8) * 128 + c0 + 9]);
        sW1h[tid] = v;
    }
    {
        int ks = (tid >> 5) & 3, mb = (tid >> 7) & 7, j = (tid >> 10) & 3, e = (tid >> 12) & 7;
        const float* s = W2 + (size_t)e * 32768;
        int oc = mb * 16 + g;
        int c0 = ks * 16 + 2 * t;
        auto chan = [&](int c) { int kp = c >> 1; return j * 64 + (kp >> 3) * 16 + (kp & 7) + (c & 1) * 8; };
        uint4 v;
        v.x = pkh(s[oc * 256 + chan(c0)],           s[oc * 256 + chan(c0 + 1)]);
        v.y = pkh(s[(oc + 8) * 256 + chan(c0)],     s[(oc + 8) * 256 + chan(c0 + 1)]);
        v.z = pkh(s[oc * 256 + chan(c0 + 8)],       s[oc * 256 + chan(c0 + 9)]);
        v.w = pkh(s[(oc + 8) * 256 + chan(c0 + 8)], s[(oc + 8) * 256 + chan(c0 + 9)]);
        sW2h[tid] = v;
    }
}

__global__ __launch_bounds__(NT, 3)
void moe_fp16(const float* __restrict__ x,
              const float* __restrict__ gate_w,
              const float* __restrict__ b1,
              const float* __restrict__ b2,
              float* __restrict__ out)
{
    extern __shared__ uint32_t smu[];
    float* smf = (float*)smu;
    const int tid  = threadIdx.x;
    const int lane = tid & 31;
    const int warp = tid >> 5;
    const int g    = lane >> 2;
    const int t    = lane & 3;
    const int wm   = warp >> 1;        // 0..3: 16-ch block (G1) / 32-oc block (G2)
    const int wn   = warp & 1;         // 0..1: 16-px block
    const int b    = blockIdx.y;
    const int p0   = blockIdx.x * TP;

    const int   e0 = g_idx[b * 2],           e1 = g_idx[b * 2 + 1];
    const float g0 = __ldg(&gate_w[b * 2]);
    const float g1 = __ldg(&gate_w[b * 2 + 1]);

    if (tid < 128)
        smf[OGB + tid] = g0 * __ldg(&b2[e0 * COUT + tid]) + g1 * __ldg(&b2[e1 * COUT + tid]);

    // ---- stage x: channel pairs packed fp16x2, px pair-permuted within 16-blocks ----
    {
        const float* xb = x + (size_t)b * CIN * HW + p0;
        int kx = tid >> 2, u = tid & 3, blk = u >> 1, sub = u & 1;
        const float* r0 = xb + (size_t)(2 * kx) * HW + blk * 16 + sub * 8;
        const float* r1 = r0 + HW;
        float4 a0 = *(const float4*)(r0);
        float4 a1 = *(const float4*)(r0 + 4);
        float4 c0 = *(const float4*)(r1);
        float4 c1 = *(const float4*)(r1 + 4);
        uint32_t* base = smu + OXS + kx * SXW + blk * 16 + sub;
        base[0]  = pkh(a0.x, c0.x);
        base[2]  = pkh(a0.y, c0.y);
        base[4]  = pkh(a0.z, c0.z);
        base[6]  = pkh(a0.w, c0.w);
        base[8]  = pkh(a1.x, c1.x);
        base[10] = pkh(a1.y, c1.y);
        base[12] = pkh(a1.z, c1.z);
        base[14] = pkh(a1.w, c1.w);
    }
    __syncthreads();

    uint32_t* const hbuf0 = smu + OHB;
    uint32_t* const hbuf1 = hbuf0 + HBSZ;

    float acc2[2][2][4];
    #pragma unroll
    for (int m = 0; m < 2; m++)
        #pragma unroll
        for (int n = 0; n < 2; n++)
            #pragma unroll
            for (int q = 0; q < 4; q++) acc2[m][n][q] = 0.f;

    #pragma unroll 1
    for (int it = 0; it < 8; it++) {
        const int   e    = (it < 4) ? e0 : e1;
        const int   j    = it & 3;
        const float gate = (it < 4) ? g0 : g1;

        // ---- GEMM1(it): D1[16ch x 16px] per warp; 8 k16-steps ----
        float acc1[2][4];
        #pragma unroll
        for (int n = 0; n < 2; n++)
            #pragma unroll
            for (int q = 0; q < 4; q++) acc1[n][q] = 0.f;
        {
            const uint4* pa = sW1h + ((e * 4 + j) * 4 + wm) * 256 + lane;
            uint4 ac = __ldg(pa);
            #pragma unroll
            for (int ks = 0; ks < 8; ks++) {
                uint4 an;
                if (ks < 7) an = __ldg(pa + (ks + 1) * 32);
                const uint32_t* xr0 = smu + OXS + (8 * ks + t) * SXW + wn * 16;
                const uint32_t* xr1 = xr0 + 4 * SXW;
                uint2 b0v = *(const uint2*)(xr0 + 2 * g);
                uint2 b1v = *(const uint2*)(xr1 + 2 * g);
                mmah(acc1[0], ac, b0v.x, b1v.x);
                mmah(acc1[1], ac, b0v.y, b1v.y);
                ac = an;
            }
        }

        // ---- GEMM2(it-1): D2[32oc x 16px] per warp; 4 k16-steps ----
        if (it > 0) {
            const int ep = (it - 1 < 4) ? e0 : e1;
            const int jp = (it - 1) & 3;
            const uint32_t* hb = ((it - 1) & 1) ? hbuf1 : hbuf0;
            const uint4* pb = sW2h + ((ep * 4 + jp) * 8 + wm * 2) * 128 + lane;
            uint4 a0c = __ldg(pb), a1c = __ldg(pb + 128);
            #pragma unroll
            for (int ks = 0; ks < 4; ks++) {
                uint4 a0n, a1n;
                if (ks < 3) { a0n = __ldg(pb + (ks + 1) * 32); a1n = __ldg(pb + 128 + (ks + 1) * 32); }
                const uint32_t* hr0 = hb + (8 * ks + t) * SHW + wn * 16;
                const uint32_t* hr1 = hr0 + 4 * SHW;
                uint2 q0 = *(const uint2*)(hr0 + 2 * g);
                uint2 q1 = *(const uint2*)(hr1 + 2 * g);
                mmah(acc2[0][0], a0c, q0.x, q1.x);
                mmah(acc2[0][1], a0c, q0.y, q1.y);
                mmah(acc2[1][0], a1c, q0.x, q1.x);
                mmah(acc2[1][1], a1c, q0.y, q1.y);
                a0c = a0n; a1c = a1n;
            }
        }

        // ---- epilogue: bias + SiLU + gate -> h[it&1], packed (g, g+8) channel pairs ----
        {
            const float bia0 = __ldg(b1 + e * CHID + j * 64 + wm * 16 + g);
            const float bia1 = __ldg(b1 + e * CHID + j * 64 + wm * 16 + 8 + g);
            uint32_t* hbw = (it & 1) ? hbuf1 : hbuf0;
            uint32_t* hrow = hbw + (8 * wm + g) * SHW;
            float hv[2][4];
            #pragma unroll
            for (int ni = 0; ni < 2; ni++) {
                float v0 = acc1[ni][0] + bia0;   // row g,   px 8ni+2t
                float v1 = acc1[ni][1] + bia0;   // row g,   px 8ni+2t+1
                float v2 = acc1[ni][2] + bia1;   // row g+8, px 8ni+2t
                float v3 = acc1[ni][3] + bia1;
                hv[ni][0] = gate * (v0 / (1.f + __expf(-v0)));
                hv[ni][1] = gate * (v1 / (1.f + __expf(-v1)));
                hv[ni][2] = gate * (v2 / (1.f + __expf(-v2)));
                hv[ni][3] = gate * (v3 / (1.f + __expf(-v3)));
            }
            // pair-permuted locs within the 16-px block: one uint4 at 4t
            uint4 wv;
            wv.x = pkh(hv[0][0], hv[0][2]);   // loc 4t:   px 2t
            wv.y = pkh(hv[1][0], hv[1][2]);   // loc 4t+1: px 8+2t
            wv.z = pkh(hv[0][1], hv[0][3]);   // loc 4t+2: px 2t+1
            wv.w = pkh(hv[1][1], hv[1][3]);   // loc 4t+3: px 9+2t
            *(uint4*)(hrow + wn * 16 + 4 * t) = wv;
        }
        __syncthreads();   // publish h(it); GEMM2(it-1) complete CTA-wide
    }

    // ---- tail: GEMM2(7) ----
    {
        const uint32_t* hb = hbuf1;
        const uint4* pb = sW2h + ((e1 * 4 + 3) * 8 + wm * 2) * 128 + lane;
        uint4 a0c = __ldg(pb), a1c = __ldg(pb + 128);
        #pragma unroll
        for (int ks = 0; ks < 4; ks++) {
            uint4 a0n, a1n;
            if (ks < 3) { a0n = __ldg(pb + (ks + 1) * 32); a1n = __ldg(pb + 128 + (ks + 1) * 32); }
            const uint32_t* hr0 = hb + (8 * ks + t) * SHW + wn * 16;
            const uint32_t* hr1 = hr0 + 4 * SHW;
            uint2 q0 = *(const uint2*)(hr0 + 2 * g);
            uint2 q1 = *(const uint2*)(hr1 + 2 * g);
            mmah(acc2[0][0], a0c, q0.x, q1.x);
            mmah(acc2[0][1], a0c, q0.y, q1.y);
            mmah(acc2[1][0], a1c, q0.x, q1.x);
            mmah(acc2[1][1], a1c, q0.y, q1.y);
            a0c = a0n; a1c = a1n;
        }
    }

    // ---- final store: acc2 + gated b2 -> out ----
    {
        float* ob = out + (size_t)b * COUT * HW + p0;
        #pragma unroll
        for (int mi = 0; mi < 2; mi++) {
            int oc = wm * 32 + 16 * mi + g;
            float gba = smf[OGB + oc], gbb = smf[OGB + oc + 8];
            #pragma unroll
            for (int ni = 0; ni < 2; ni++) {
                int px = wn * 16 + 8 * ni + 2 * t;
                *(float2*)(ob + (size_t)oc * HW + px) =
                    make_float2(acc2[mi][ni][0] + gba, acc2[mi][ni][1] + gba);
                *(float2*)(ob + (size_t)(oc + 8) * HW + px) =
                    make_float2(acc2[mi][ni][2] + gbb, acc2[mi][ni][3] + gbb);
            }
        }
    }
}

extern "C" void kernel_launch(void* const* d_in, const int* in_sizes, int n_in,
                              void* d_out, int out_size) {
    const float* x   = (const float*)d_in[0];
    const float* wts = (const float*)d_in[1];
    const int*   idx = (const int*)d_in[2];
    const float* W1  = (const float*)d_in[3];
    const float* b1  = (const float*)d_in[4];
    const float* W2  = (const float*)d_in[5];
    const float* b2  = (const float*)d_in[6];
    float* out = (float*)d_out;
    (void)in_sizes; (void)n_in; (void)out_size;

    prep_idx<<<1, 256>>>(idx);
    prep_wh<<<64, 512>>>(W1, W2);

    cudaFuncSetAttribute(moe_fp16, cudaFuncAttributeMaxDynamicSharedMemorySize, SMB);
    dim3 grid(NTILE, 128);
    moe_fp16<<<grid, NT, SMB>>>(x, wts, b1, b2, out);
}

// round 17
// speedup vs baseline: 1.3792x; 1.3792x over previous
#include <cuda_runtime.h>
#include <cuda_fp16.h>
#include <cstdint>

#define CIN   128
#define CHID  256
#define COUT  128
#define HW    1600
#define TP    64
#define NT    256
#define NTILE 25

#define SXW 72     // x row stride in u32 words (mod 32 == 8 -> conflict-free LDS.64)
#define SHW 40     // h row stride in u32 words

// SMEM u32-word offsets
#define OXS 0                        // x  [64 kpair][72] u32 (fp16x2, px pair-permuted)
#define OHB 4608                     // h: 2 halves x 2 bufs x [32 kpair][40]
#define HBSZ 1280
#define OGB 9728                     // gated b2 [128] (float view)
#define SMB ((9728 + 128) * 4)       // 39424 B -> 2 CTAs/SM

// weights packed as fp16 MMA A-fragments (one uint4 per lane per k16-step), 512KB each
__device__ uint4 sW1h[32768];
__device__ uint4 sW2h[32768];
__device__ int   g_idx[256];

__device__ __forceinline__ uint32_t pkh(float a, float b) {
    __half2 h = __floats2half2_rn(a, b);   // low = a
    return *reinterpret_cast<uint32_t*>(&h);
}
__device__ __forceinline__ float tanh_ap(float v) {
    float r;
    asm("tanh.approx.f32 %0, %1;" : "=f"(r) : "f"(v));
    return r;
}
// gate * silu(v) = gate * v * sigmoid(v) = gm + gm * tanh(v/2), gm = gate*v/2
__device__ __forceinline__ float gsilu(float v, float gate) {
    float u = 0.5f * v;
    float t = tanh_ap(u);
    float gm = gate * u;
    return fmaf(gm, t, gm);
}
__device__ __forceinline__ void mmah(float (&d)[4], const uint4& a, uint32_t b0, uint32_t b1) {
    asm("mma.sync.aligned.m16n8k16.row.col.f32.f16.f16.f32 "
        "{%0,%1,%2,%3}, {%4,%5,%6,%7}, {%8,%9}, {%0,%1,%2,%3};"
        : "+f"(d[0]), "+f"(d[1]), "+f"(d[2]), "+f"(d[3])
        : "r"(a.x), "r"(a.y), "r"(a.z), "r"(a.w), "r"(b0), "r"(b1));
}
#define HBAR(id) asm volatile("bar.sync %0, 128;" :: "r"(id) : "memory")

__global__ void prep_idx(const int* __restrict__ raw) {
    __shared__ int odd_nz;
    if (threadIdx.x == 0) odd_nz = 0;
    __syncthreads();
    if (threadIdx.x < 128) {
        if (raw[2 * threadIdx.x + 1] != 0) atomicAdd(&odd_nz, 1);
    }
    __syncthreads();
    bool is64 = (odd_nz == 0);
    g_idx[threadIdx.x] = is64 ? raw[2 * threadIdx.x] : raw[threadIdx.x];
}

// Pack weights into fp16 A-fragment order (identical to R14).
__global__ void prep_wh(const float* __restrict__ W1, const float* __restrict__ W2) {
    int tid = blockIdx.x * blockDim.x + threadIdx.x;    // 0..32767
    int lane = tid & 31, g = lane >> 2, t = lane & 3;
    {
        int ks = (tid >> 5) & 7, wm = (tid >> 8) & 3, j = (tid >> 10) & 3, e = (tid >> 12) & 7;
        const float* s = W1 + (size_t)e * 32768;
        int ch = j * 64 + wm * 16 + g;
        int c0 = ks * 16 + 2 * t;
        uint4 v;
        v.x = pkh(s[ch * 128 + c0],           s[ch * 128 + c0 + 1]);
        v.y = pkh(s[(ch + 8) * 128 + c0],     s[(ch + 8) * 128 + c0 + 1]);
        v.z = pkh(s[ch * 128 + c0 + 8],       s[ch * 128 + c0 + 9]);
        v.w = pkh(s[(ch + 8) * 128 + c0 + 8], s[(ch + 8) * 128 + c0 + 9]);
        sW1h[tid] = v;
    }
    {
        int ks = (tid >> 5) & 3, mb = (tid >> 7) & 7, j = (tid >> 10) & 3, e = (tid >> 12) & 7;
        const float* s = W2 + (size_t)e * 32768;
        int oc = mb * 16 + g;
        int c0 = ks * 16 + 2 * t;
        auto chan = [&](int c) { int kp = c >> 1; return j * 64 + (kp >> 3) * 16 + (kp & 7) + (c & 1) * 8; };
        uint4 v;
        v.x = pkh(s[oc * 256 + chan(c0)],           s[oc * 256 + chan(c0 + 1)]);
        v.y = pkh(s[(oc + 8) * 256 + chan(c0)],     s[(oc + 8) * 256 + chan(c0 + 1)]);
        v.z = pkh(s[oc * 256 + chan(c0 + 8)],       s[oc * 256 + chan(c0 + 9)]);
        v.w = pkh(s[(oc + 8) * 256 + chan(c0 + 8)], s[(oc + 8) * 256 + chan(c0 + 9)]);
        sW2h[tid] = v;
    }
}

__global__ __launch_bounds__(NT, 2)
void moe_fp16(const float* __restrict__ x,
              const float* __restrict__ gate_w,
              const float* __restrict__ b1,
              const float* __restrict__ b2,
              float* __restrict__ out)
{
    extern __shared__ uint32_t smu[];
    float* smf = (float*)smu;
    const int tid  = threadIdx.x;
    const int lane = tid & 31;
    const int warp = tid >> 5;
    const int g    = lane >> 2;
    const int t    = lane & 3;
    const int hf   = warp >> 2;        // half: 0 -> px [0,32), 1 -> px [32,64)
    const int wm   = warp & 3;
    const int b    = blockIdx.y;
    const int p0   = blockIdx.x * TP;

    const int   e0 = g_idx[b * 2],           e1 = g_idx[b * 2 + 1];
    const float g0 = __ldg(&gate_w[b * 2]);
    const float g1 = __ldg(&gate_w[b * 2 + 1]);

    if (tid < 128)
        smf[OGB + tid] = g0 * __ldg(&b2[e0 * COUT + tid]) + g1 * __ldg(&b2[e1 * COUT + tid]);

    // ---- stage x: channel pairs packed fp16x2, px pair-permuted within 16-blocks ----
    {
        const float* xb = x + (size_t)b * CIN * HW + p0;
        int kx = tid >> 2, blk = tid & 3;
        const float* r0 = xb + (size_t)(2 * kx) * HW + blk * 16;
        const float* r1 = r0 + HW;
        uint32_t w[16];
        #pragma unroll
        for (int q = 0; q < 4; q++) {
            float4 u0 = *(const float4*)(r0 + 4 * q);
            float4 u1 = *(const float4*)(r1 + 4 * q);
            w[4 * q + 0] = pkh(u0.x, u1.x);
            w[4 * q + 1] = pkh(u0.y, u1.y);
            w[4 * q + 2] = pkh(u0.z, u1.z);
            w[4 * q + 3] = pkh(u0.w, u1.w);
        }
        uint4* dst = (uint4*)(smu + OXS + kx * SXW + blk * 16);
        dst[0] = make_uint4(w[0], w[8],  w[1], w[9]);
        dst[1] = make_uint4(w[2], w[10], w[3], w[11]);
        dst[2] = make_uint4(w[4], w[12], w[5], w[13]);
        dst[3] = make_uint4(w[6], w[14], w[7], w[15]);
    }
    __syncthreads();

    uint32_t* const hbuf0 = smu + OHB + hf * 2 * HBSZ;
    uint32_t* const hbuf1 = hbuf0 + HBSZ;

    float acc2[2][4][4];
    #pragma unroll
    for (int m = 0; m < 2; m++)
        #pragma unroll
        for (int n = 0; n < 4; n++)
            #pragma unroll
            for (int q = 0; q < 4; q++) acc2[m][n][q] = 0.f;

    #pragma unroll 1
    for (int it = 0; it < 8; it++) {
        const int   e    = (it < 4) ? e0 : e1;
        const int   j    = it & 3;
        const float gate = (it < 4) ? g0 : g1;

        // ---- GEMM1(it): D1[16ch x 32px] per warp; 8 k16-steps ----
        float acc1[4][4];
        #pragma unroll
        for (int n = 0; n < 4; n++)
            #pragma unroll
            for (int q = 0; q < 4; q++) acc1[n][q] = 0.f;
        {
            const uint4* pa = sW1h + ((e * 4 + j) * 4 + wm) * 256 + lane;
            uint4 ac = __ldg(pa);
            #pragma unroll
            for (int ks = 0; ks < 8; ks++) {
                uint4 an;
                if (ks < 7) an = __ldg(pa + (ks + 1) * 32);
                const uint32_t* xr0 = smu + OXS + (8 * ks + t) * SXW + hf * 32;
                const uint32_t* xr1 = xr0 + 4 * SXW;
                uint2 b00 = *(const uint2*)(xr0 + 2 * g);
                uint2 b10 = *(const uint2*)(xr1 + 2 * g);
                uint2 b01 = *(const uint2*)(xr0 + 16 + 2 * g);
                uint2 b11 = *(const uint2*)(xr1 + 16 + 2 * g);
                mmah(acc1[0], ac, b00.x, b10.x);
                mmah(acc1[1], ac, b00.y, b10.y);
                mmah(acc1[2], ac, b01.x, b11.x);
                mmah(acc1[3], ac, b01.y, b11.y);
                ac = an;
            }
        }

        // ---- GEMM2(it-1): D2[32oc x 32px] per warp; 4 k16-steps, permuted k ----
        if (it > 0) {
            const int ep = (it - 1 < 4) ? e0 : e1;
            const int jp = (it - 1) & 3;
            const uint32_t* hb = ((it - 1) & 1) ? hbuf1 : hbuf0;
            const uint4* pb = sW2h + ((ep * 4 + jp) * 8 + wm * 2) * 128 + lane;
            uint4 a0c = __ldg(pb), a1c = __ldg(pb + 128);
            #pragma unroll
            for (int ks = 0; ks < 4; ks++) {
                uint4 a0n, a1n;
                if (ks < 3) { a0n = __ldg(pb + (ks + 1) * 32); a1n = __ldg(pb + 128 + (ks + 1) * 32); }
                const uint32_t* hr0 = hb + (8 * ks + t) * SHW;
                const uint32_t* hr1 = hr0 + 4 * SHW;
                uint2 q00 = *(const uint2*)(hr0 + 2 * g);
                uint2 q10 = *(const uint2*)(hr1 + 2 * g);
                uint2 q01 = *(const uint2*)(hr0 + 16 + 2 * g);
                uint2 q11 = *(const uint2*)(hr1 + 16 + 2 * g);
                mmah(acc2[0][0], a0c, q00.x, q10.x);
                mmah(acc2[0][1], a0c, q00.y, q10.y);
                mmah(acc2[0][2], a0c, q01.x, q11.x);
                mmah(acc2[0][3], a0c, q01.y, q11.y);
                mmah(acc2[1][0], a1c, q00.x, q10.x);
                mmah(acc2[1][1], a1c, q00.y, q10.y);
                mmah(acc2[1][2], a1c, q01.x, q11.x);
                mmah(acc2[1][3], a1c, q01.y, q11.y);
                a0c = a0n; a1c = a1n;
            }
        }

        // ---- epilogue: bias + SiLU(tanh) + gate -> h[it&1], packed channel pairs ----
        {
            const float bia0 = __ldg(b1 + e * CHID + j * 64 + wm * 16 + g);
            const float bia1 = __ldg(b1 + e * CHID + j * 64 + wm * 16 + 8 + g);
            uint32_t* hbw = (it & 1) ? hbuf1 : hbuf0;
            uint32_t* hrow = hbw + (8 * wm + g) * SHW;
            #pragma unroll
            for (int ni = 0; ni < 4; ni++) {
                int loc = (ni >> 1) * 16 + 4 * t + (ni & 1);
                float h0 = gsilu(acc1[ni][0] + bia0, gate);
                float h1 = gsilu(acc1[ni][1] + bia0, gate);
                float h2 = gsilu(acc1[ni][2] + bia1, gate);
                float h3 = gsilu(acc1[ni][3] + bia1, gate);
                hrow[loc]     = pkh(h0, h2);
                hrow[loc + 2] = pkh(h1, h3);
            }
        }
        HBAR(hf + 1);   // publish h(it) within this 4-warp half
    }

    // ---- tail: GEMM2(7) ----
    {
        const uint32_t* hb = hbuf1;
        const uint4* pb = sW2h + ((e1 * 4 + 3) * 8 + wm * 2) * 128 + lane;
        uint4 a0c = __ldg(pb), a1c = __ldg(pb + 128);
        #pragma unroll
        for (int ks = 0; ks < 4; ks++) {
            uint4 a0n, a1n;
            if (ks < 3) { a0n = __ldg(pb + (ks + 1) * 32); a1n = __ldg(pb + 128 + (ks + 1) * 32); }
            const uint32_t* hr0 = hb + (8 * ks + t) * SHW;
            const uint32_t* hr1 = hr0 + 4 * SHW;
            uint2 q00 = *(const uint2*)(hr0 + 2 * g);
            uint2 q10 = *(const uint2*)(hr1 + 2 * g);
            uint2 q01 = *(const uint2*)(hr0 + 16 + 2 * g);
            uint2 q11 = *(const uint2*)(hr1 + 16 + 2 * g);
            mmah(acc2[0][0], a0c, q00.x, q10.x);
            mmah(acc2[0][1], a0c, q00.y, q10.y);
            mmah(acc2[0][2], a0c, q01.x, q11.x);
            mmah(acc2[0][3], a0c, q01.y, q11.y);
            mmah(acc2[1][0], a1c, q00.x, q10.x);
            mmah(acc2[1][1], a1c, q00.y, q10.y);
            mmah(acc2[1][2], a1c, q01.x, q11.x);
            mmah(acc2[1][3], a1c, q01.y, q11.y);
            a0c = a0n; a1c = a1n;
        }
    }

    // ---- final store: acc2 + gated b2 -> out ----
    {
        float* ob = out + (size_t)b * COUT * HW + p0 + hf * 32;
        #pragma unroll
        for (int mi = 0; mi < 2; mi++) {
            int oc = wm * 32 + 16 * mi + g;
            float gba = smf[OGB + oc], gbb = smf[OGB + oc + 8];
            #pragma unroll
            for (int ni = 0; ni < 4; ni++) {
                int px = 8 * ni + 2 * t;
                *(float2*)(ob + (size_t)oc * HW + px) =
                    make_float2(acc2[mi][ni][0] + gba, acc2[mi][ni][1] + gba);
                *(float2*)(ob + (size_t)(oc + 8) * HW + px) =
                    make_float2(acc2[mi][ni][2] + gbb, acc2[mi][ni][3] + gbb);
            }
        }
    }
}

extern "C" void kernel_launch(void* const* d_in, const int* in_sizes, int n_in,
                              void* d_out, int out_size) {
    const float* x   = (const float*)d_in[0];
    const float* wts = (const float*)d_in[1];
    const int*   idx = (const int*)d_in[2];
    const float* W1  = (const float*)d_in[3];
    const float* b1  = (const float*)d_in[4];
    const float* W2  = (const float*)d_in[5];
    const float* b2  = (const float*)d_in[6];
    float* out = (float*)d_out;
    (void)in_sizes; (void)n_in; (void)out_size;

    prep_idx<<<1, 256>>>(idx);
    prep_wh<<<64, 512>>>(W1, W2);

    cudaFuncSetAttribute(moe_fp16, cudaFuncAttributeMaxDynamicSharedMemorySize, SMB);
    dim3 grid(NTILE, 128);
    moe_fp16<<<grid, NT, SMB>>>(x, wts, b1, b2, out);
}